// round 1
// baseline (speedup 1.0000x reference)
#include <cuda_runtime.h>
#include <cstdint>
#include <cstddef>

#define NN 32768
#define NE 327680
#define BB 64
#define SS 512
#define OC 192
#define H4 768
#define QC 576

// ---------------- scratch (static device globals; no allocations) ----------------
__device__ float g_xw  [NN * 192];
__device__ float g_h   [NN * 192];
__device__ float g_xih [(size_t)NN * H4];
__device__ float g_lstm[NN * OC];
__device__ float g_qkv [NN * QC];
__device__ float g_attn[NN * OC];
__device__ float g_dinv[NN];
__device__ int   g_deg [NN];
__device__ float g_norm[NE];
__device__ float g_wihT[192 * H4];
__device__ float g_whhT[192 * H4];
__device__ float g_inT [192 * QC];
__device__ float g_gbias[H4];
__device__ float g_obar[BB * OC];

// ---------------- small helpers ----------------
__device__ __forceinline__ unsigned long long pk2(float a, float b) {
    unsigned long long r;
    asm("mov.b64 %0, {%1,%2};" : "=l"(r) : "f"(a), "f"(b));
    return r;
}
__device__ __forceinline__ void upk2(unsigned long long v, float& a, float& b) {
    asm("mov.b64 {%0,%1}, %2;" : "=f"(a), "=f"(b) : "l"(v));
}
__device__ __forceinline__ void fma2(unsigned long long& acc, unsigned long long a, unsigned long long b) {
    asm("fma.rn.f32x2 %0, %1, %2, %0;" : "+l"(acc) : "l"(a), "l"(b));
}
__device__ __forceinline__ float sigf(float x) { return 1.0f / (1.0f + __expf(-x)); }

// ---------------- prep kernels ----------------
__global__ void transpose_k(const float* __restrict__ in, float* __restrict__ out, int R, int C) {
    int idx = blockIdx.x * blockDim.x + threadIdx.x;
    if (idx < R * C) {
        int r = idx / C, c = idx % C;
        out[c * R + r] = in[idx];
    }
}
__global__ void bias_sum_k(const float* __restrict__ a, const float* __restrict__ b,
                           float* __restrict__ out, int n) {
    int i = blockIdx.x * blockDim.x + threadIdx.x;
    if (i < n) out[i] = a[i] + b[i];
}
__global__ void zero_i32_k(int* p, int n) {
    int i = blockIdx.x * blockDim.x + threadIdx.x;
    if (i < n) p[i] = 0;
}
__global__ void count_deg_k(const int* __restrict__ ei, int* __restrict__ deg) {
    int e = blockIdx.x * blockDim.x + threadIdx.x;
    if (e < NE) atomicAdd(&deg[ei[NE + e]], 1);
}
__global__ void calc_dinv_k(const int* __restrict__ deg, float* __restrict__ dinv) {
    int n = blockIdx.x * blockDim.x + threadIdx.x;
    if (n < NN) dinv[n] = rsqrtf((float)(deg[n] + 1));  // +1 self loop
}
__global__ void calc_norm_k(const int* __restrict__ ei, const float* __restrict__ dinv,
                            float* __restrict__ nrm) {
    int e = blockIdx.x * blockDim.x + threadIdx.x;
    if (e < NE) nrm[e] = dinv[ei[e]] * dinv[ei[NE + e]];
}

// ---------------- SGEMM: C[M,N] = op(A[M,K]) @ B[K,N] (+bias) ----------------
#define GBM 64
#define GBN 64
#define GBK 16
template <bool RELU_A, bool BIAS>
__global__ __launch_bounds__(256) void sgemm_kernel(
    const float* __restrict__ A, const float* __restrict__ Bm,
    const float* __restrict__ bias, float* __restrict__ C,
    int M, int N, int K) {
    __shared__ float As[GBK][GBM + 4];
    __shared__ float Bs[GBK][GBN];
    int tid = threadIdx.x;
    int tx = tid & 15, ty = tid >> 4;
    int row0 = blockIdx.y * GBM, col0 = blockIdx.x * GBN;
    int arow = tid >> 2, acol = (tid & 3) * 4;
    int brow = tid >> 4, bcol = (tid & 15) * 4;
    float acc[4][4] = {};
    for (int k0 = 0; k0 < K; k0 += GBK) {
        float4 av = *(const float4*)(A + (size_t)(row0 + arow) * K + k0 + acol);
        if (RELU_A) {
            av.x = fmaxf(av.x, 0.f); av.y = fmaxf(av.y, 0.f);
            av.z = fmaxf(av.z, 0.f); av.w = fmaxf(av.w, 0.f);
        }
        As[acol + 0][arow] = av.x; As[acol + 1][arow] = av.y;
        As[acol + 2][arow] = av.z; As[acol + 3][arow] = av.w;
        *(float4*)&Bs[brow][bcol] = *(const float4*)(Bm + (size_t)(k0 + brow) * N + col0 + bcol);
        __syncthreads();
#pragma unroll
        for (int k = 0; k < GBK; k++) {
            float4 a = *(const float4*)&As[k][ty * 4];
            float4 b = *(const float4*)&Bs[k][tx * 4];
            acc[0][0] += a.x * b.x; acc[0][1] += a.x * b.y; acc[0][2] += a.x * b.z; acc[0][3] += a.x * b.w;
            acc[1][0] += a.y * b.x; acc[1][1] += a.y * b.y; acc[1][2] += a.y * b.z; acc[1][3] += a.y * b.w;
            acc[2][0] += a.z * b.x; acc[2][1] += a.z * b.y; acc[2][2] += a.z * b.z; acc[2][3] += a.z * b.w;
            acc[3][0] += a.w * b.x; acc[3][1] += a.w * b.y; acc[3][2] += a.w * b.z; acc[3][3] += a.w * b.w;
        }
        __syncthreads();
    }
    float4 bv = make_float4(0.f, 0.f, 0.f, 0.f);
    if (BIAS) bv = *(const float4*)(bias + col0 + tx * 4);
#pragma unroll
    for (int i = 0; i < 4; i++) {
        float4 r = make_float4(acc[i][0] + bv.x, acc[i][1] + bv.y, acc[i][2] + bv.z, acc[i][3] + bv.w);
        *(float4*)(C + (size_t)(row0 + ty * 4 + i) * N + col0 + tx * 4) = r;
    }
}

// ---------------- GCN scatter ----------------
__global__ void gcn_init_k(const float* __restrict__ xw, const float* __restrict__ bias,
                           const float* __restrict__ dinv, float* __restrict__ out, int C) {
    int idx = blockIdx.x * blockDim.x + threadIdx.x;
    if (idx < NN * C) {
        int n = idx / C, c = idx % C;
        float di = dinv[n];
        out[idx] = bias[c] + di * di * xw[idx];
    }
}
__global__ void gcn_scatter_k(const float* __restrict__ xw, const int* __restrict__ ei,
                              const float* __restrict__ nrm, float* __restrict__ out, int C4) {
    int idx = blockIdx.x * blockDim.x + threadIdx.x;
    int total = NE * C4;
    if (idx >= total) return;
    int e = idx / C4, cc = idx % C4;
    int s = ei[e], d = ei[NE + e];
    float w = nrm[e];
    int C = C4 * 4;
    float4 v = *(const float4*)(xw + (size_t)s * C + cc * 4);
    float* o = out + (size_t)d * C + cc * 4;
    atomicAdd(o + 0, w * v.x);
    atomicAdd(o + 1, w * v.y);
    atomicAdd(o + 2, w * v.z);
    atomicAdd(o + 3, w * v.w);
}

// ---------------- LSTM: 32 blocks, 2 batches each, f32x2-packed recurrence ----------------
#define LSTM_KC 72
#define LSTM_SMEM (192 * 8 + LSTM_KC * H4 * 4)
__global__ __launch_bounds__(192, 1) void lstm_kernel(
    const float* __restrict__ xih, const float* __restrict__ whhT, float* __restrict__ out) {
    extern __shared__ float smem[];
    float2* h2 = (float2*)smem;            // 192 float2
    float* wc = smem + 192 * 2;            // LSTM_KC * 768 floats
    int j = threadIdx.x;
    int b0 = blockIdx.x * 2, b1 = b0 + 1;
    for (int i = j; i < LSTM_KC * H4; i += 192) wc[i] = whhT[i];
    h2[j] = make_float2(0.f, 0.f);
    float c0 = 0.f, c1 = 0.f;
    __syncthreads();
    const float* x0 = xih + (size_t)b0 * SS * H4;
    const float* x1 = xih + (size_t)b1 * SS * H4;
    float* o0 = out + (size_t)b0 * SS * OC;
    float* o1 = out + (size_t)b1 * SS * OC;
    for (int t = 0; t < SS; t++) {
        const float* xr0 = x0 + t * H4;
        const float* xr1 = x1 + t * H4;
        unsigned long long a0 = pk2(xr0[j],        xr1[j]);
        unsigned long long a1 = pk2(xr0[192 + j],  xr1[192 + j]);
        unsigned long long a2 = pk2(xr0[384 + j],  xr1[384 + j]);
        unsigned long long a3 = pk2(xr0[576 + j],  xr1[576 + j]);
#pragma unroll 4
        for (int k = 0; k < LSTM_KC; k++) {
            float2 h = h2[k];
            unsigned long long hp = pk2(h.x, h.y);
            const float* w = wc + k * H4 + j;
            fma2(a0, pk2(w[0],   w[0]),   hp);
            fma2(a1, pk2(w[192], w[192]), hp);
            fma2(a2, pk2(w[384], w[384]), hp);
            fma2(a3, pk2(w[576], w[576]), hp);
        }
#pragma unroll 4
        for (int k = LSTM_KC; k < 192; k++) {
            float2 h = h2[k];
            unsigned long long hp = pk2(h.x, h.y);
            const float* w = whhT + (size_t)k * H4 + j;
            float w0 = __ldg(w), w1 = __ldg(w + 192), w2 = __ldg(w + 384), w3 = __ldg(w + 576);
            fma2(a0, pk2(w0, w0), hp);
            fma2(a1, pk2(w1, w1), hp);
            fma2(a2, pk2(w2, w2), hp);
            fma2(a3, pk2(w3, w3), hp);
        }
        float iA, iB, fA, fB, gA, gB, oA, oB;
        upk2(a0, iA, iB); upk2(a1, fA, fB); upk2(a2, gA, gB); upk2(a3, oA, oB);
        c0 = sigf(fA) * c0 + sigf(iA) * tanhf(gA);
        c1 = sigf(fB) * c1 + sigf(iB) * tanhf(gB);
        float hA = sigf(oA) * tanhf(c0);
        float hB = sigf(oB) * tanhf(c1);
        __syncthreads();
        h2[j] = make_float2(hA, hB);
        o0[t * OC + j] = hA;
        o1[t * OC + j] = hB;
        __syncthreads();
    }
}

// ---------------- attention: one CTA per (b, head) ----------------
#define AT_PAD 36
#define AT_SMEM (2 * SS * AT_PAD * 4)
__global__ __launch_bounds__(256, 1) void attn_kernel(
    const float* __restrict__ qkv, float* __restrict__ outp) {
    extern __shared__ float sm[];
    float* Ks = sm;
    float* Vs = sm + SS * AT_PAD;
    int bh = blockIdx.x;
    int b = bh / 6, h = bh % 6;
    int tid = threadIdx.x;
    const float* base = qkv + (size_t)b * SS * QC;
    for (int i = tid; i < SS * 8; i += 256) {
        int r = i >> 3, d4 = (i & 7) * 4;
        *(float4*)(Ks + r * AT_PAD + d4) = *(const float4*)(base + (size_t)r * QC + 192 + h * 32 + d4);
        *(float4*)(Vs + r * AT_PAD + d4) = *(const float4*)(base + (size_t)r * QC + 384 + h * 32 + d4);
    }
    __syncthreads();
    int wid = tid >> 5, lane = tid & 31;
    const float scale = 0.17677669529663689f;  // 1/sqrt(32)
    for (int qi = wid; qi < SS; qi += 8) {
        const float* qr = base + (size_t)qi * QC + h * 32;
        float q[32];
#pragma unroll
        for (int d4 = 0; d4 < 8; d4++) {
            float4 v = *(const float4*)(qr + d4 * 4);
            q[d4 * 4 + 0] = v.x * scale; q[d4 * 4 + 1] = v.y * scale;
            q[d4 * 4 + 2] = v.z * scale; q[d4 * 4 + 3] = v.w * scale;
        }
        float s[16];
#pragma unroll
        for (int jj = 0; jj < 16; jj++) {
            const float* kr = Ks + (jj * 32 + lane) * AT_PAD;
            float a = 0.f;
#pragma unroll
            for (int d4 = 0; d4 < 8; d4++) {
                float4 kv = *(const float4*)(kr + d4 * 4);
                a += q[d4 * 4 + 0] * kv.x + q[d4 * 4 + 1] * kv.y +
                     q[d4 * 4 + 2] * kv.z + q[d4 * 4 + 3] * kv.w;
            }
            s[jj] = a;
        }
        float mx = -1e30f;
#pragma unroll
        for (int jj = 0; jj < 16; jj++) mx = fmaxf(mx, s[jj]);
#pragma unroll
        for (int off = 16; off; off >>= 1) mx = fmaxf(mx, __shfl_xor_sync(0xffffffffu, mx, off));
        float sum = 0.f;
#pragma unroll
        for (int jj = 0; jj < 16; jj++) { s[jj] = __expf(s[jj] - mx); sum += s[jj]; }
#pragma unroll
        for (int off = 16; off; off >>= 1) sum += __shfl_xor_sync(0xffffffffu, sum, off);
        float inv = 1.0f / sum;
        float o[32] = {};
#pragma unroll
        for (int jj = 0; jj < 16; jj++) {
            float p = s[jj] * inv;
            const float* vr = Vs + (jj * 32 + lane) * AT_PAD;
#pragma unroll
            for (int d4 = 0; d4 < 8; d4++) {
                float4 vv = *(const float4*)(vr + d4 * 4);
                o[d4 * 4 + 0] += p * vv.x; o[d4 * 4 + 1] += p * vv.y;
                o[d4 * 4 + 2] += p * vv.z; o[d4 * 4 + 3] += p * vv.w;
            }
        }
#pragma unroll
        for (int d = 0; d < 32; d++) {
            float v = o[d];
            v += __shfl_down_sync(0xffffffffu, v, 16);
            v += __shfl_down_sync(0xffffffffu, v, 8);
            v += __shfl_down_sync(0xffffffffu, v, 4);
            v += __shfl_down_sync(0xffffffffu, v, 2);
            v += __shfl_down_sync(0xffffffffu, v, 1);
            o[d] = v;
        }
        if (lane == 0) {
            float* orow = outp + (size_t)(b * SS + qi) * OC + h * 32;
#pragma unroll
            for (int d4 = 0; d4 < 8; d4++)
                *(float4*)(orow + d4 * 4) =
                    make_float4(o[d4 * 4], o[d4 * 4 + 1], o[d4 * 4 + 2], o[d4 * 4 + 3]);
        }
    }
}

// ---------------- mean over time + final projection ----------------
__global__ void mean_kernel(const float* __restrict__ attn, float* __restrict__ obar) {
    int b = blockIdx.x, c = threadIdx.x;  // 192 threads
    float s = 0.f;
    for (int t = 0; t < SS; t++) s += attn[(size_t)(b * SS + t) * OC + c];
    obar[b * OC + c] = s * (1.0f / SS);
}
__global__ void final_proj_kernel(const float* __restrict__ obar, const float* __restrict__ W,
                                  const float* __restrict__ bias, float* __restrict__ out) {
    __shared__ float sx[OC];
    int b = blockIdx.x, c = threadIdx.x;  // 192 threads
    sx[c] = obar[b * OC + c];
    __syncthreads();
    float acc = 0.f;
    const float* wr = W + c * OC;
    for (int k = 0; k < OC; k++) acc += sx[k] * wr[k];
    out[b * OC + c] = acc + bias[c];
}

// ---------------- launch ----------------
extern "C" void kernel_launch(void* const* d_in, const int* in_sizes, int n_in,
                              void* d_out, int out_size) {
    const float* x    = (const float*)d_in[0];
    const int*   ei   = (const int*)d_in[1];
    const float* W0   = (const float*)d_in[3];
    const float* b0   = (const float*)d_in[4];
    const float* W1   = (const float*)d_in[5];
    const float* b1   = (const float*)d_in[6];
    const float* W2   = (const float*)d_in[7];
    const float* b2   = (const float*)d_in[8];
    const float* wih  = (const float*)d_in[9];
    const float* whh  = (const float*)d_in[10];
    const float* bih  = (const float*)d_in[11];
    const float* bhh  = (const float*)d_in[12];
    const float* inW  = (const float*)d_in[13];
    const float* inB  = (const float*)d_in[14];
    const float* outW = (const float*)d_in[15];
    const float* outB = (const float*)d_in[16];
    float* out = (float*)d_out;

    float *xw, *hb, *xih, *lstm, *qkv, *attn, *dinv, *nrm, *wihT, *whhT, *inT, *gbias, *obar;
    int* deg;
    cudaGetSymbolAddress((void**)&xw, g_xw);
    cudaGetSymbolAddress((void**)&hb, g_h);
    cudaGetSymbolAddress((void**)&xih, g_xih);
    cudaGetSymbolAddress((void**)&lstm, g_lstm);
    cudaGetSymbolAddress((void**)&qkv, g_qkv);
    cudaGetSymbolAddress((void**)&attn, g_attn);
    cudaGetSymbolAddress((void**)&dinv, g_dinv);
    cudaGetSymbolAddress((void**)&deg, g_deg);
    cudaGetSymbolAddress((void**)&nrm, g_norm);
    cudaGetSymbolAddress((void**)&wihT, g_wihT);
    cudaGetSymbolAddress((void**)&whhT, g_whhT);
    cudaGetSymbolAddress((void**)&inT, g_inT);
    cudaGetSymbolAddress((void**)&gbias, g_gbias);
    cudaGetSymbolAddress((void**)&obar, g_obar);

    cudaFuncSetAttribute(lstm_kernel, cudaFuncAttributeMaxDynamicSharedMemorySize, LSTM_SMEM);
    cudaFuncSetAttribute(attn_kernel, cudaFuncAttributeMaxDynamicSharedMemorySize, AT_SMEM);

    // prep: weight transposes + fused lstm bias + graph norm
    transpose_k<<<(H4 * 192 + 255) / 256, 256>>>(wih, wihT, H4, 192);
    transpose_k<<<(H4 * 192 + 255) / 256, 256>>>(whh, whhT, H4, 192);
    transpose_k<<<(QC * 192 + 255) / 256, 256>>>(inW, inT, QC, 192);
    bias_sum_k<<<(H4 + 255) / 256, 256>>>(bih, bhh, gbias, H4);
    zero_i32_k<<<(NN + 255) / 256, 256>>>(deg, NN);
    count_deg_k<<<(NE + 255) / 256, 256>>>(ei, deg);
    calc_dinv_k<<<(NN + 255) / 256, 256>>>(deg, dinv);
    calc_norm_k<<<(NE + 255) / 256, 256>>>(ei, dinv, nrm);

    // GCN layer 1: [N,128]@[128,128]
    sgemm_kernel<false, false><<<dim3(128 / GBN, NN / GBM), 256>>>(x, W0, nullptr, xw, NN, 128, 128);
    gcn_init_k<<<(NN * 128 + 255) / 256, 256>>>(xw, b0, dinv, hb, 128);
    gcn_scatter_k<<<(NE * 32 + 255) / 256, 256>>>(xw, ei, nrm, hb, 32);
    // GCN layer 2
    sgemm_kernel<true, false><<<dim3(128 / GBN, NN / GBM), 256>>>(hb, W1, nullptr, xw, NN, 128, 128);
    gcn_init_k<<<(NN * 128 + 255) / 256, 256>>>(xw, b1, dinv, hb, 128);
    gcn_scatter_k<<<(NE * 32 + 255) / 256, 256>>>(xw, ei, nrm, hb, 32);
    // GCN layer 3: [N,128]@[128,192]
    sgemm_kernel<true, false><<<dim3(192 / GBN, NN / GBM), 256>>>(hb, W2, nullptr, xw, NN, 192, 128);
    gcn_init_k<<<(NN * 192 + 255) / 256, 256>>>(xw, b2, dinv, hb, 192);
    gcn_scatter_k<<<(NE * 48 + 255) / 256, 256>>>(xw, ei, nrm, hb, 48);

    // LSTM input precompute: relu(h3) @ wihT + (b_ih+b_hh)  -> [N,768]
    sgemm_kernel<true, true><<<dim3(H4 / GBN, NN / GBM), 256>>>(hb, wihT, gbias, xih, NN, H4, 192);
    // LSTM recurrence
    lstm_kernel<<<32, 192, LSTM_SMEM>>>(xih, whhT, lstm);
    // QKV projection
    sgemm_kernel<false, true><<<dim3(QC / GBN, NN / GBM), 256>>>(lstm, inT, inB, qkv, NN, QC, 192);
    // attention
    attn_kernel<<<BB * 6, 256, AT_SMEM>>>(qkv, attn);
    // mean over sequence, then tiny output projection (mean commutes with linear)
    mean_kernel<<<BB, OC>>>(attn, obar);
    final_proj_kernel<<<BB, OC>>>(obar, outW, outB, out);
}

// round 2
// speedup vs baseline: 2.1288x; 2.1288x over previous
#include <cuda_runtime.h>
#include <cstdint>
#include <cstddef>

#define NN 32768
#define NE 327680
#define BB 64
#define SS 512
#define OC 192
#define H4 768
#define QC 576

// ---------------- scratch (static device globals; no allocations) ----------------
__device__ float g_xw  [NN * 192];
__device__ float g_h   [NN * 192];
__device__ float g_xih [(size_t)NN * H4];
__device__ float g_lstm[NN * OC];
__device__ float g_qkv [NN * QC];
__device__ float g_attn[NN * OC];
__device__ float g_dinv[NN];
__device__ int   g_deg [NN];
__device__ float g_norm[NE];
__device__ float g_wihT[192 * H4];
__device__ float g_whhT[192 * H4];
__device__ float g_inT [192 * QC];
__device__ float g_gbias[H4];
__device__ float g_obar[BB * OC];

// ---------------- small helpers ----------------
__device__ __forceinline__ unsigned long long pk2(float a, float b) {
    unsigned long long r;
    asm("mov.b64 %0, {%1,%2};" : "=l"(r) : "f"(a), "f"(b));
    return r;
}
__device__ __forceinline__ float sigf(float x) { return 1.0f / (1.0f + __expf(-x)); }
__device__ __forceinline__ uint32_t smem_u32(const void* p) {
    uint32_t a;
    asm("{ .reg .u64 t; cvta.to.shared.u64 t, %1; cvt.u32.u64 %0, t; }" : "=r"(a) : "l"(p));
    return a;
}
#define CLUSTER_SYNC() do { \
    asm volatile("barrier.cluster.arrive.aligned;" ::: "memory"); \
    asm volatile("barrier.cluster.wait.aligned;" ::: "memory"); \
} while (0)

// ---------------- prep kernels ----------------
__global__ void transpose_k(const float* __restrict__ in, float* __restrict__ out, int R, int C) {
    int idx = blockIdx.x * blockDim.x + threadIdx.x;
    if (idx < R * C) {
        int r = idx / C, c = idx % C;
        out[c * R + r] = in[idx];
    }
}
__global__ void bias_sum_k(const float* __restrict__ a, const float* __restrict__ b,
                           float* __restrict__ out, int n) {
    int i = blockIdx.x * blockDim.x + threadIdx.x;
    if (i < n) out[i] = a[i] + b[i];
}
__global__ void zero_i32_k(int* p, int n) {
    int i = blockIdx.x * blockDim.x + threadIdx.x;
    if (i < n) p[i] = 0;
}
__global__ void count_deg_k(const int* __restrict__ ei, int* __restrict__ deg) {
    int e = blockIdx.x * blockDim.x + threadIdx.x;
    if (e < NE) atomicAdd(&deg[ei[NE + e]], 1);
}
__global__ void calc_dinv_k(const int* __restrict__ deg, float* __restrict__ dinv) {
    int n = blockIdx.x * blockDim.x + threadIdx.x;
    if (n < NN) dinv[n] = rsqrtf((float)(deg[n] + 1));  // +1 self loop
}
__global__ void calc_norm_k(const int* __restrict__ ei, const float* __restrict__ dinv,
                            float* __restrict__ nrm) {
    int e = blockIdx.x * blockDim.x + threadIdx.x;
    if (e < NE) nrm[e] = dinv[ei[e]] * dinv[ei[NE + e]];
}

// ---------------- SGEMM 128x64x16 double-buffered: C = op(A) @ B (+bias) ----------------
#define TM 128
#define TN 64
#define TK 16
template <bool RELU_A, bool BIAS>
__global__ __launch_bounds__(256) void sgemm2(
    const float* __restrict__ A, const float* __restrict__ Bm,
    const float* __restrict__ bias, float* __restrict__ C,
    int M, int N, int K) {
    __shared__ float As[2][TK][TM + 4];
    __shared__ float Bs[2][TK][TN];
    int tid = threadIdx.x;
    int row0 = blockIdx.y * TM, col0 = blockIdx.x * TN;
    int arow = tid >> 2, acol = (tid & 3) * 4;
    int brow = tid >> 4, bcol = (tid & 15) * 4;
    int tx = tid & 15, ty = tid >> 4;
    const float* Abase = A + (size_t)row0 * K;
    const float* Bbase = Bm + col0;

    // load chunk 0
    {
        float4 a0 = *(const float4*)(Abase + (size_t)arow * K + acol);
        float4 a1 = *(const float4*)(Abase + (size_t)(arow + 64) * K + acol);
        if (RELU_A) {
            a0.x = fmaxf(a0.x, 0.f); a0.y = fmaxf(a0.y, 0.f); a0.z = fmaxf(a0.z, 0.f); a0.w = fmaxf(a0.w, 0.f);
            a1.x = fmaxf(a1.x, 0.f); a1.y = fmaxf(a1.y, 0.f); a1.z = fmaxf(a1.z, 0.f); a1.w = fmaxf(a1.w, 0.f);
        }
        As[0][acol + 0][arow] = a0.x; As[0][acol + 1][arow] = a0.y;
        As[0][acol + 2][arow] = a0.z; As[0][acol + 3][arow] = a0.w;
        As[0][acol + 0][arow + 64] = a1.x; As[0][acol + 1][arow + 64] = a1.y;
        As[0][acol + 2][arow + 64] = a1.z; As[0][acol + 3][arow + 64] = a1.w;
        *(float4*)&Bs[0][brow][bcol] = *(const float4*)(Bbase + (size_t)brow * N + bcol);
    }
    __syncthreads();

    float acc[8][4] = {};
    int nc = K / TK;
    float4 pa0, pa1, pb;
    for (int c = 0; c < nc; c++) {
        int s = c & 1;
        if (c + 1 < nc) {
            int k0 = (c + 1) * TK;
            pa0 = *(const float4*)(Abase + (size_t)arow * K + k0 + acol);
            pa1 = *(const float4*)(Abase + (size_t)(arow + 64) * K + k0 + acol);
            pb  = *(const float4*)(Bbase + (size_t)(k0 + brow) * N + bcol);
            if (RELU_A) {
                pa0.x = fmaxf(pa0.x, 0.f); pa0.y = fmaxf(pa0.y, 0.f); pa0.z = fmaxf(pa0.z, 0.f); pa0.w = fmaxf(pa0.w, 0.f);
                pa1.x = fmaxf(pa1.x, 0.f); pa1.y = fmaxf(pa1.y, 0.f); pa1.z = fmaxf(pa1.z, 0.f); pa1.w = fmaxf(pa1.w, 0.f);
            }
        }
#pragma unroll
        for (int k = 0; k < TK; k++) {
            float4 a0v = *(const float4*)&As[s][k][ty * 8];
            float4 a1v = *(const float4*)&As[s][k][ty * 8 + 4];
            float4 bv  = *(const float4*)&Bs[s][k][tx * 4];
            float am[8] = {a0v.x, a0v.y, a0v.z, a0v.w, a1v.x, a1v.y, a1v.z, a1v.w};
#pragma unroll
            for (int i = 0; i < 8; i++) {
                acc[i][0] = fmaf(am[i], bv.x, acc[i][0]);
                acc[i][1] = fmaf(am[i], bv.y, acc[i][1]);
                acc[i][2] = fmaf(am[i], bv.z, acc[i][2]);
                acc[i][3] = fmaf(am[i], bv.w, acc[i][3]);
            }
        }
        if (c + 1 < nc) {
            int d = s ^ 1;
            As[d][acol + 0][arow] = pa0.x; As[d][acol + 1][arow] = pa0.y;
            As[d][acol + 2][arow] = pa0.z; As[d][acol + 3][arow] = pa0.w;
            As[d][acol + 0][arow + 64] = pa1.x; As[d][acol + 1][arow + 64] = pa1.y;
            As[d][acol + 2][arow + 64] = pa1.z; As[d][acol + 3][arow + 64] = pa1.w;
            *(float4*)&Bs[d][brow][bcol] = pb;
        }
        __syncthreads();
    }

    float4 bv = make_float4(0.f, 0.f, 0.f, 0.f);
    if (BIAS) bv = *(const float4*)(bias + col0 + tx * 4);
#pragma unroll
    for (int i = 0; i < 8; i++) {
        float4 r = make_float4(acc[i][0] + bv.x, acc[i][1] + bv.y, acc[i][2] + bv.z, acc[i][3] + bv.w);
        *(float4*)(C + (size_t)(row0 + ty * 8 + i) * N + col0 + tx * 4) = r;
    }
}

// ---------------- GCN scatter ----------------
__global__ void gcn_init_k(const float* __restrict__ xw, const float* __restrict__ bias,
                           const float* __restrict__ dinv, float* __restrict__ out, int C) {
    int idx = blockIdx.x * blockDim.x + threadIdx.x;
    if (idx < NN * C) {
        int n = idx / C, c = idx % C;
        float di = dinv[n];
        out[idx] = bias[c] + di * di * xw[idx];
    }
}
template <int C4>
__global__ void gcn_scatter_k(const float* __restrict__ xw, const int* __restrict__ ei,
                              const float* __restrict__ nrm, float* __restrict__ out) {
    int idx = blockIdx.x * blockDim.x + threadIdx.x;
    if (idx >= NE * C4) return;
    int e = idx / C4, cc = idx % C4;
    int s = ei[e], d = ei[NE + e];
    float w = nrm[e];
    const int C = C4 * 4;
    float4 v = *(const float4*)(xw + (size_t)s * C + cc * 4);
    float* o = out + (size_t)d * C + cc * 4;
    asm volatile("red.global.add.v4.f32 [%0], {%1,%2,%3,%4};"
                 :: "l"(o), "f"(w * v.x), "f"(w * v.y), "f"(w * v.z), "f"(w * v.w)
                 : "memory");
}

// ---------------- LSTM: cluster-of-4 K-split, 2 batches per cluster ----------------
// CTA rank r holds whh rows k in [48r, 48r+48) fully in smem (147KB).
// Per step: each CTA computes partial gate sums for all 768 gate rows over its k-slice,
// pushes them to the owner CTA (owner of hidden unit u = u/48) via DSMEM, barrier,
// owners update c/h for their 48 units and broadcast h to all 4 CTAs, barrier.
#define LSTM_SMEM (48 * 768 * 4 + 192 * 8 + 4 * 192 * 8)
__global__ __launch_bounds__(768, 1) __cluster_dims__(4, 1, 1)
void lstm_cluster_kernel(const float* __restrict__ xih, const float* __restrict__ whhT,
                         float* __restrict__ out) {
    extern __shared__ float sm[];
    float* ws = sm;                               // paired weights: [24][768][2]
    float2* h01 = (float2*)(sm + 48 * 768);       // h for (b0,b1), 192 units
    float2* gb = h01 + 192;                       // partial gates [4 src][192 slots]
    int tid = threadIdx.x;
    uint32_t rank;
    asm("mov.u32 %0, %%cluster_ctarank;" : "=r"(rank));
    int cid = blockIdx.x >> 2;
    int b0 = cid * 2;

    // weight slice, k-pair interleaved: ws[p*1536 + j*2 + e] = whh[j][48*rank + 2p + e]
#pragma unroll 4
    for (int p = 0; p < 24; p++) {
        ws[p * 1536 + tid * 2 + 0] = whhT[(size_t)(rank * 48 + 2 * p + 0) * 768 + tid];
        ws[p * 1536 + tid * 2 + 1] = whhT[(size_t)(rank * 48 + 2 * p + 1) * 768 + tid];
    }
    if (tid < 192) h01[tid] = make_float2(0.f, 0.f);

    // push target: owner of gate-row j=tid is rank (j%192)/48, slot (j/192)*48 + (j%192)%48
    int j = tid;
    int gidx = j / 192, u192 = j % 192;
    uint32_t ro = (uint32_t)(u192 / 48);
    int slot = gidx * 48 + (u192 % 48);
    uint32_t gb_local = smem_u32(&gb[rank * 192 + slot]);
    uint32_t gb_remote;
    asm("mapa.shared::cluster.u32 %0, %1, %2;" : "=r"(gb_remote) : "r"(gb_local), "r"(ro));

    // consume state (threads 0..47 own hidden units 48*rank + tid)
    float2 c01 = make_float2(0.f, 0.f);
    int unit = rank * 48 + tid;
    uint32_t hrem[4];
    if (tid < 48) {
        uint32_t hl = smem_u32(&h01[unit]);
#pragma unroll
        for (uint32_t rr = 0; rr < 4; rr++)
            asm("mapa.shared::cluster.u32 %0, %1, %2;" : "=r"(hrem[rr]) : "r"(hl), "r"(rr));
    }
    const float* x0 = xih + (size_t)b0 * SS * H4;
    const float* x1 = x0 + (size_t)SS * H4;
    float* o0 = out + (size_t)b0 * SS * OC;
    float* o1 = o0 + (size_t)SS * OC;
    const int hb = (int)rank * 48;

    CLUSTER_SYNC();
    for (int t = 0; t < SS; t++) {
        // partial gate sums over this CTA's k slice
        float acc0 = 0.f, acc1 = 0.f;
        const float* wrow = ws + tid * 2;
#pragma unroll
        for (int p = 0; p < 24; p++) {
            float4 h2 = *(const float4*)&h01[hb + 2 * p];   // (h0[2p],h1[2p],h0[2p+1],h1[2p+1])
            float2 wp = *(const float2*)&wrow[p * 1536];
            acc0 = fmaf(wp.x, h2.x, acc0);
            acc1 = fmaf(wp.x, h2.y, acc1);
            acc0 = fmaf(wp.y, h2.z, acc0);
            acc1 = fmaf(wp.y, h2.w, acc1);
        }
        unsigned long long pv = pk2(acc0, acc1);
        asm volatile("st.shared::cluster.b64 [%0], %1;" :: "r"(gb_remote), "l"(pv) : "memory");
        CLUSTER_SYNC();
        if (tid < 48) {
            float pre0[4], pre1[4];
#pragma unroll
            for (int g = 0; g < 4; g++) {
                float2 s0 = gb[0 * 192 + g * 48 + tid];
                float2 s1 = gb[1 * 192 + g * 48 + tid];
                float2 s2 = gb[2 * 192 + g * 48 + tid];
                float2 s3 = gb[3 * 192 + g * 48 + tid];
                pre0[g] = s0.x + s1.x + s2.x + s3.x + x0[(size_t)t * H4 + g * 192 + unit];
                pre1[g] = s0.y + s1.y + s2.y + s3.y + x1[(size_t)t * H4 + g * 192 + unit];
            }
            float i0 = sigf(pre0[0]), f0 = sigf(pre0[1]), g0 = tanhf(pre0[2]), oo0 = sigf(pre0[3]);
            float i1 = sigf(pre1[0]), f1 = sigf(pre1[1]), g1 = tanhf(pre1[2]), oo1 = sigf(pre1[3]);
            c01.x = f0 * c01.x + i0 * g0;
            c01.y = f1 * c01.y + i1 * g1;
            float h0v = oo0 * tanhf(c01.x);
            float h1v = oo1 * tanhf(c01.y);
            unsigned long long hp = pk2(h0v, h1v);
#pragma unroll
            for (int rr = 0; rr < 4; rr++)
                asm volatile("st.shared::cluster.b64 [%0], %1;" :: "r"(hrem[rr]), "l"(hp) : "memory");
            o0[(size_t)t * OC + unit] = h0v;
            o1[(size_t)t * OC + unit] = h1v;
        }
        CLUSTER_SYNC();
    }
}

// ---------------- attention: one CTA per (b, head) ----------------
#define AT_PAD 36
#define AT_SMEM (2 * SS * AT_PAD * 4)
__global__ __launch_bounds__(256, 1) void attn_kernel(
    const float* __restrict__ qkv, float* __restrict__ outp) {
    extern __shared__ float sm[];
    float* Ks = sm;
    float* Vs = sm + SS * AT_PAD;
    int bh = blockIdx.x;
    int b = bh / 6, h = bh % 6;
    int tid = threadIdx.x;
    const float* base = qkv + (size_t)b * SS * QC;
    for (int i = tid; i < SS * 8; i += 256) {
        int r = i >> 3, d4 = (i & 7) * 4;
        *(float4*)(Ks + r * AT_PAD + d4) = *(const float4*)(base + (size_t)r * QC + 192 + h * 32 + d4);
        *(float4*)(Vs + r * AT_PAD + d4) = *(const float4*)(base + (size_t)r * QC + 384 + h * 32 + d4);
    }
    __syncthreads();
    int wid = tid >> 5, lane = tid & 31;
    const float scale = 0.17677669529663689f;  // 1/sqrt(32)
    for (int qi = wid; qi < SS; qi += 8) {
        const float* qr = base + (size_t)qi * QC + h * 32;
        float q[32];
#pragma unroll
        for (int d4 = 0; d4 < 8; d4++) {
            float4 v = *(const float4*)(qr + d4 * 4);
            q[d4 * 4 + 0] = v.x * scale; q[d4 * 4 + 1] = v.y * scale;
            q[d4 * 4 + 2] = v.z * scale; q[d4 * 4 + 3] = v.w * scale;
        }
        float s[16];
#pragma unroll
        for (int jj = 0; jj < 16; jj++) {
            const float* kr = Ks + (jj * 32 + lane) * AT_PAD;
            float a = 0.f;
#pragma unroll
            for (int d4 = 0; d4 < 8; d4++) {
                float4 kv = *(const float4*)(kr + d4 * 4);
                a += q[d4 * 4 + 0] * kv.x + q[d4 * 4 + 1] * kv.y +
                     q[d4 * 4 + 2] * kv.z + q[d4 * 4 + 3] * kv.w;
            }
            s[jj] = a;
        }
        float mx = -1e30f;
#pragma unroll
        for (int jj = 0; jj < 16; jj++) mx = fmaxf(mx, s[jj]);
#pragma unroll
        for (int off = 16; off; off >>= 1) mx = fmaxf(mx, __shfl_xor_sync(0xffffffffu, mx, off));
        float sum = 0.f;
#pragma unroll
        for (int jj = 0; jj < 16; jj++) { s[jj] = __expf(s[jj] - mx); sum += s[jj]; }
#pragma unroll
        for (int off = 16; off; off >>= 1) sum += __shfl_xor_sync(0xffffffffu, sum, off);
        float inv = 1.0f / sum;
        float o[32] = {};
#pragma unroll
        for (int jj = 0; jj < 16; jj++) {
            float p = s[jj] * inv;
            const float* vr = Vs + (jj * 32 + lane) * AT_PAD;
#pragma unroll
            for (int d4 = 0; d4 < 8; d4++) {
                float4 vv = *(const float4*)(vr + d4 * 4);
                o[d4 * 4 + 0] += p * vv.x; o[d4 * 4 + 1] += p * vv.y;
                o[d4 * 4 + 2] += p * vv.z; o[d4 * 4 + 3] += p * vv.w;
            }
        }
#pragma unroll
        for (int d = 0; d < 32; d++) {
            float v = o[d];
            v += __shfl_down_sync(0xffffffffu, v, 16);
            v += __shfl_down_sync(0xffffffffu, v, 8);
            v += __shfl_down_sync(0xffffffffu, v, 4);
            v += __shfl_down_sync(0xffffffffu, v, 2);
            v += __shfl_down_sync(0xffffffffu, v, 1);
            o[d] = v;
        }
        if (lane == 0) {
            float* orow = outp + (size_t)(b * SS + qi) * OC + h * 32;
#pragma unroll
            for (int d4 = 0; d4 < 8; d4++)
                *(float4*)(orow + d4 * 4) =
                    make_float4(o[d4 * 4], o[d4 * 4 + 1], o[d4 * 4 + 2], o[d4 * 4 + 3]);
        }
    }
}

// ---------------- mean over time + final projection ----------------
__global__ void mean_kernel(const float* __restrict__ attn, float* __restrict__ obar) {
    int b = blockIdx.x, c = threadIdx.x;  // 192 threads
    float s = 0.f;
    for (int t = 0; t < SS; t++) s += attn[(size_t)(b * SS + t) * OC + c];
    obar[b * OC + c] = s * (1.0f / SS);
}
__global__ void final_proj_kernel(const float* __restrict__ obar, const float* __restrict__ W,
                                  const float* __restrict__ bias, float* __restrict__ out) {
    __shared__ float sx[OC];
    int b = blockIdx.x, c = threadIdx.x;  // 192 threads
    sx[c] = obar[b * OC + c];
    __syncthreads();
    float acc = 0.f;
    const float* wr = W + c * OC;
    for (int k = 0; k < OC; k++) acc += sx[k] * wr[k];
    out[b * OC + c] = acc + bias[c];
}

// ---------------- launch ----------------
extern "C" void kernel_launch(void* const* d_in, const int* in_sizes, int n_in,
                              void* d_out, int out_size) {
    const float* x    = (const float*)d_in[0];
    const int*   ei   = (const int*)d_in[1];
    const float* W0   = (const float*)d_in[3];
    const float* b0   = (const float*)d_in[4];
    const float* W1   = (const float*)d_in[5];
    const float* b1   = (const float*)d_in[6];
    const float* W2   = (const float*)d_in[7];
    const float* b2   = (const float*)d_in[8];
    const float* wih  = (const float*)d_in[9];
    const float* whh  = (const float*)d_in[10];
    const float* bih  = (const float*)d_in[11];
    const float* bhh  = (const float*)d_in[12];
    const float* inW  = (const float*)d_in[13];
    const float* inB  = (const float*)d_in[14];
    const float* outW = (const float*)d_in[15];
    const float* outB = (const float*)d_in[16];
    float* out = (float*)d_out;

    float *xw, *hb, *xih, *lstm, *qkv, *attn, *dinv, *nrm, *wihT, *whhT, *inT, *gbias, *obar;
    int* deg;
    cudaGetSymbolAddress((void**)&xw, g_xw);
    cudaGetSymbolAddress((void**)&hb, g_h);
    cudaGetSymbolAddress((void**)&xih, g_xih);
    cudaGetSymbolAddress((void**)&lstm, g_lstm);
    cudaGetSymbolAddress((void**)&qkv, g_qkv);
    cudaGetSymbolAddress((void**)&attn, g_attn);
    cudaGetSymbolAddress((void**)&dinv, g_dinv);
    cudaGetSymbolAddress((void**)&deg, g_deg);
    cudaGetSymbolAddress((void**)&nrm, g_norm);
    cudaGetSymbolAddress((void**)&wihT, g_wihT);
    cudaGetSymbolAddress((void**)&whhT, g_whhT);
    cudaGetSymbolAddress((void**)&inT, g_inT);
    cudaGetSymbolAddress((void**)&gbias, g_gbias);
    cudaGetSymbolAddress((void**)&obar, g_obar);

    cudaFuncSetAttribute(lstm_cluster_kernel, cudaFuncAttributeMaxDynamicSharedMemorySize, LSTM_SMEM);
    cudaFuncSetAttribute(attn_kernel, cudaFuncAttributeMaxDynamicSharedMemorySize, AT_SMEM);

    // prep: weight transposes + fused lstm bias + graph norm
    transpose_k<<<(H4 * 192 + 255) / 256, 256>>>(wih, wihT, H4, 192);
    transpose_k<<<(H4 * 192 + 255) / 256, 256>>>(whh, whhT, H4, 192);
    transpose_k<<<(QC * 192 + 255) / 256, 256>>>(inW, inT, QC, 192);
    bias_sum_k<<<(H4 + 255) / 256, 256>>>(bih, bhh, gbias, H4);
    zero_i32_k<<<(NN + 255) / 256, 256>>>(deg, NN);
    count_deg_k<<<(NE + 255) / 256, 256>>>(ei, deg);
    calc_dinv_k<<<(NN + 255) / 256, 256>>>(deg, dinv);
    calc_norm_k<<<(NE + 255) / 256, 256>>>(ei, dinv, nrm);

    // GCN layer 1: [N,128]@[128,128]
    sgemm2<false, false><<<dim3(128 / TN, NN / TM), 256>>>(x, W0, nullptr, xw, NN, 128, 128);
    gcn_init_k<<<(NN * 128 + 255) / 256, 256>>>(xw, b0, dinv, hb, 128);
    gcn_scatter_k<32><<<(NE * 32 + 255) / 256, 256>>>(xw, ei, nrm, hb);
    // GCN layer 2
    sgemm2<true, false><<<dim3(128 / TN, NN / TM), 256>>>(hb, W1, nullptr, xw, NN, 128, 128);
    gcn_init_k<<<(NN * 128 + 255) / 256, 256>>>(xw, b1, dinv, hb, 128);
    gcn_scatter_k<32><<<(NE * 32 + 255) / 256, 256>>>(xw, ei, nrm, hb);
    // GCN layer 3: [N,128]@[128,192]
    sgemm2<true, false><<<dim3(192 / TN, NN / TM), 256>>>(hb, W2, nullptr, xw, NN, 192, 128);
    gcn_init_k<<<(NN * 192 + 255) / 256, 256>>>(xw, b2, dinv, hb, 192);
    gcn_scatter_k<48><<<(NE * 48 + 255) / 256, 256>>>(xw, ei, nrm, hb);

    // LSTM input precompute: relu(h3) @ wihT + (b_ih+b_hh)  -> [N,768]
    sgemm2<true, true><<<dim3(H4 / TN, NN / TM), 256>>>(hb, wihT, gbias, xih, NN, H4, 192);
    // LSTM recurrence: 32 clusters x 4 CTAs (compile-time cluster dims)
    lstm_cluster_kernel<<<128, 768, LSTM_SMEM>>>(xih, whhT, lstm);
    // QKV projection
    sgemm2<false, true><<<dim3(QC / TN, NN / TM), 256>>>(lstm, inT, inB, qkv, NN, QC, 192);
    // attention
    attn_kernel<<<BB * 6, 256, AT_SMEM>>>(qkv, attn);
    // mean over sequence, then tiny output projection (mean commutes with linear)
    mean_kernel<<<BB, OC>>>(attn, obar);
    final_proj_kernel<<<BB, OC>>>(obar, outW, outB, out);
}

// round 3
// speedup vs baseline: 2.4533x; 1.1525x over previous
#include <cuda_runtime.h>
#include <cstdint>
#include <cstddef>

#define NN 32768
#define NE 327680
#define BB 64
#define SS 512
#define OC 192
#define H4 768
#define QC 576

// ---------------- scratch (static device globals; no allocations) ----------------
__device__ float g_xw  [NN * 192];
__device__ float g_h   [NN * 192];
__device__ float g_xih [(size_t)NN * H4];
__device__ float g_lstm[NN * OC];
__device__ float g_qkv [NN * QC];
__device__ float g_attn[NN * OC];
__device__ float g_dinv[NN];
__device__ int   g_deg [NN];
__device__ float g_norm[NE];
__device__ float g_wihT[192 * H4];
__device__ float g_whhT[192 * H4];
__device__ float g_inT [192 * QC];
__device__ float g_gbias[H4];

// ---------------- small helpers ----------------
__device__ __forceinline__ unsigned long long pk2(float a, float b) {
    unsigned long long r;
    asm("mov.b64 %0, {%1,%2};" : "=l"(r) : "f"(a), "f"(b));
    return r;
}
__device__ __forceinline__ float sigf(float x) { return 1.0f / (1.0f + __expf(-x)); }
__device__ __forceinline__ uint32_t smem_u32(const void* p) {
    uint32_t a;
    asm("{ .reg .u64 t; cvta.to.shared.u64 t, %1; cvt.u32.u64 %0, t; }" : "=r"(a) : "l"(p));
    return a;
}
#define CLUSTER_SYNC() do { \
    asm volatile("barrier.cluster.arrive.aligned;" ::: "memory"); \
    asm volatile("barrier.cluster.wait.aligned;" ::: "memory"); \
} while (0)

// ---------------- fused prep: 3 transposes + lstm bias ----------------
__global__ void prep_k(const float* __restrict__ wih, const float* __restrict__ whh,
                       const float* __restrict__ inW, const float* __restrict__ bih,
                       const float* __restrict__ bhh,
                       float* __restrict__ wihT, float* __restrict__ whhT,
                       float* __restrict__ inT, float* __restrict__ gbias) {
    int idx = blockIdx.x * blockDim.x + threadIdx.x;
    const int T1 = H4 * 192;
    const int T2 = 2 * T1;
    const int T3 = T2 + QC * 192;
    const int T4 = T3 + H4;
    if (idx < T1) {
        int r = idx / 192, c = idx % 192;
        wihT[c * H4 + r] = wih[idx];
    } else if (idx < T2) {
        int j = idx - T1;
        int r = j / 192, c = j % 192;
        whhT[c * H4 + r] = whh[j];
    } else if (idx < T3) {
        int j = idx - T2;
        int r = j / 192, c = j % 192;
        inT[c * QC + r] = inW[j];
    } else if (idx < T4) {
        int j = idx - T3;
        gbias[j] = bih[j] + bhh[j];
    }
}
__global__ void zero_i32_k(int* p, int n) {
    int i = blockIdx.x * blockDim.x + threadIdx.x;
    if (i < n) p[i] = 0;
}
__global__ void count_deg_k(const int* __restrict__ ei, int* __restrict__ deg) {
    int e = blockIdx.x * blockDim.x + threadIdx.x;
    if (e < NE) atomicAdd(&deg[ei[NE + e]], 1);
}
__global__ void calc_dinv_k(const int* __restrict__ deg, float* __restrict__ dinv) {
    int n = blockIdx.x * blockDim.x + threadIdx.x;
    if (n < NN) dinv[n] = rsqrtf((float)(deg[n] + 1));  // +1 self loop
}
__global__ void calc_norm_k(const int* __restrict__ ei, const float* __restrict__ dinv,
                            float* __restrict__ nrm) {
    int e = blockIdx.x * blockDim.x + threadIdx.x;
    if (e < NE) nrm[e] = dinv[ei[e]] * dinv[ei[NE + e]];
}

// ---------------- SGEMM 128x64x16 double-buffered: C = op(A) @ B (+bias) ----------------
#define TM 128
#define TN 64
#define TK 16
template <bool RELU_A, bool BIAS>
__global__ __launch_bounds__(256) void sgemm2(
    const float* __restrict__ A, const float* __restrict__ Bm,
    const float* __restrict__ bias, float* __restrict__ C,
    int M, int N, int K) {
    __shared__ float As[2][TK][TM + 4];
    __shared__ float Bs[2][TK][TN];
    int tid = threadIdx.x;
    int row0 = blockIdx.y * TM, col0 = blockIdx.x * TN;
    int arow = tid >> 2, acol = (tid & 3) * 4;
    int brow = tid >> 4, bcol = (tid & 15) * 4;
    int tx = tid & 15, ty = tid >> 4;
    const float* Abase = A + (size_t)row0 * K;
    const float* Bbase = Bm + col0;

    {
        float4 a0 = *(const float4*)(Abase + (size_t)arow * K + acol);
        float4 a1 = *(const float4*)(Abase + (size_t)(arow + 64) * K + acol);
        if (RELU_A) {
            a0.x = fmaxf(a0.x, 0.f); a0.y = fmaxf(a0.y, 0.f); a0.z = fmaxf(a0.z, 0.f); a0.w = fmaxf(a0.w, 0.f);
            a1.x = fmaxf(a1.x, 0.f); a1.y = fmaxf(a1.y, 0.f); a1.z = fmaxf(a1.z, 0.f); a1.w = fmaxf(a1.w, 0.f);
        }
        As[0][acol + 0][arow] = a0.x; As[0][acol + 1][arow] = a0.y;
        As[0][acol + 2][arow] = a0.z; As[0][acol + 3][arow] = a0.w;
        As[0][acol + 0][arow + 64] = a1.x; As[0][acol + 1][arow + 64] = a1.y;
        As[0][acol + 2][arow + 64] = a1.z; As[0][acol + 3][arow + 64] = a1.w;
        *(float4*)&Bs[0][brow][bcol] = *(const float4*)(Bbase + (size_t)brow * N + bcol);
    }
    __syncthreads();

    float acc[8][4] = {};
    int nc = K / TK;
    float4 pa0, pa1, pb;
    for (int c = 0; c < nc; c++) {
        int s = c & 1;
        if (c + 1 < nc) {
            int k0 = (c + 1) * TK;
            pa0 = *(const float4*)(Abase + (size_t)arow * K + k0 + acol);
            pa1 = *(const float4*)(Abase + (size_t)(arow + 64) * K + k0 + acol);
            pb  = *(const float4*)(Bbase + (size_t)(k0 + brow) * N + bcol);
            if (RELU_A) {
                pa0.x = fmaxf(pa0.x, 0.f); pa0.y = fmaxf(pa0.y, 0.f); pa0.z = fmaxf(pa0.z, 0.f); pa0.w = fmaxf(pa0.w, 0.f);
                pa1.x = fmaxf(pa1.x, 0.f); pa1.y = fmaxf(pa1.y, 0.f); pa1.z = fmaxf(pa1.z, 0.f); pa1.w = fmaxf(pa1.w, 0.f);
            }
        }
#pragma unroll
        for (int k = 0; k < TK; k++) {
            float4 a0v = *(const float4*)&As[s][k][ty * 8];
            float4 a1v = *(const float4*)&As[s][k][ty * 8 + 4];
            float4 bv  = *(const float4*)&Bs[s][k][tx * 4];
            float am[8] = {a0v.x, a0v.y, a0v.z, a0v.w, a1v.x, a1v.y, a1v.z, a1v.w};
#pragma unroll
            for (int i = 0; i < 8; i++) {
                acc[i][0] = fmaf(am[i], bv.x, acc[i][0]);
                acc[i][1] = fmaf(am[i], bv.y, acc[i][1]);
                acc[i][2] = fmaf(am[i], bv.z, acc[i][2]);
                acc[i][3] = fmaf(am[i], bv.w, acc[i][3]);
            }
        }
        if (c + 1 < nc) {
            int d = s ^ 1;
            As[d][acol + 0][arow] = pa0.x; As[d][acol + 1][arow] = pa0.y;
            As[d][acol + 2][arow] = pa0.z; As[d][acol + 3][arow] = pa0.w;
            As[d][acol + 0][arow + 64] = pa1.x; As[d][acol + 1][arow + 64] = pa1.y;
            As[d][acol + 2][arow + 64] = pa1.z; As[d][acol + 3][arow + 64] = pa1.w;
            *(float4*)&Bs[d][brow][bcol] = pb;
        }
        __syncthreads();
    }

    float4 bv = make_float4(0.f, 0.f, 0.f, 0.f);
    if (BIAS) bv = *(const float4*)(bias + col0 + tx * 4);
#pragma unroll
    for (int i = 0; i < 8; i++) {
        float4 r = make_float4(acc[i][0] + bv.x, acc[i][1] + bv.y, acc[i][2] + bv.z, acc[i][3] + bv.w);
        *(float4*)(C + (size_t)(row0 + ty * 8 + i) * N + col0 + tx * 4) = r;
    }
}

// ---------------- GCN scatter ----------------
__global__ void gcn_init_k(const float* __restrict__ xw, const float* __restrict__ bias,
                           const float* __restrict__ dinv, float* __restrict__ out, int C) {
    int idx = blockIdx.x * blockDim.x + threadIdx.x;
    if (idx < NN * C) {
        int n = idx / C, c = idx % C;
        float di = dinv[n];
        out[idx] = bias[c] + di * di * xw[idx];
    }
}
template <int C4>
__global__ void gcn_scatter_k(const float* __restrict__ xw, const int* __restrict__ ei,
                              const float* __restrict__ nrm, float* __restrict__ out) {
    int idx = blockIdx.x * blockDim.x + threadIdx.x;
    if (idx >= NE * C4) return;
    int e = idx / C4, cc = idx % C4;
    int s = ei[e], d = ei[NE + e];
    float w = nrm[e];
    const int C = C4 * 4;
    float4 v = *(const float4*)(xw + (size_t)s * C + cc * 4);
    float* o = out + (size_t)d * C + cc * 4;
    asm volatile("red.global.add.v4.f32 [%0], {%1,%2,%3,%4};"
                 :: "l"(o), "f"(w * v.x), "f"(w * v.y), "f"(w * v.z), "f"(w * v.w)
                 : "memory");
}

// ---------------- LSTM: cluster-of-4 K-split, 2 batches per cluster ----------------
#define LSTM_SMEM (48 * 768 * 4 + 192 * 8 + 4 * 192 * 8)
__global__ __launch_bounds__(768, 1) __cluster_dims__(4, 1, 1)
void lstm_cluster_kernel(const float* __restrict__ xih, const float* __restrict__ whhT,
                         float* __restrict__ out) {
    extern __shared__ float sm[];
    float* ws = sm;                               // paired weights: [24][768][2]
    float2* h01 = (float2*)(sm + 48 * 768);       // h for (b0,b1), 192 units
    float2* gb = h01 + 192;                       // partial gates [4 src][192 slots]
    int tid = threadIdx.x;
    uint32_t rank;
    asm("mov.u32 %0, %%cluster_ctarank;" : "=r"(rank));
    int cid = blockIdx.x >> 2;
    int b0 = cid * 2;

#pragma unroll 4
    for (int p = 0; p < 24; p++) {
        ws[p * 1536 + tid * 2 + 0] = whhT[(size_t)(rank * 48 + 2 * p + 0) * 768 + tid];
        ws[p * 1536 + tid * 2 + 1] = whhT[(size_t)(rank * 48 + 2 * p + 1) * 768 + tid];
    }
    if (tid < 192) h01[tid] = make_float2(0.f, 0.f);

    int j = tid;
    int gidx = j / 192, u192 = j % 192;
    uint32_t ro = (uint32_t)(u192 / 48);
    int slot = gidx * 48 + (u192 % 48);
    uint32_t gb_local = smem_u32(&gb[rank * 192 + slot]);
    uint32_t gb_remote;
    asm("mapa.shared::cluster.u32 %0, %1, %2;" : "=r"(gb_remote) : "r"(gb_local), "r"(ro));

    float2 c01 = make_float2(0.f, 0.f);
    int unit = rank * 48 + tid;
    uint32_t hrem[4];
    if (tid < 48) {
        uint32_t hl = smem_u32(&h01[unit]);
#pragma unroll
        for (uint32_t rr = 0; rr < 4; rr++)
            asm("mapa.shared::cluster.u32 %0, %1, %2;" : "=r"(hrem[rr]) : "r"(hl), "r"(rr));
    }
    const float* x0 = xih + (size_t)b0 * SS * H4;
    const float* x1 = x0 + (size_t)SS * H4;
    float* o0 = out + (size_t)b0 * SS * OC;
    float* o1 = o0 + (size_t)SS * OC;
    const int hb = (int)rank * 48;

    // prefetch x gate inputs for t=0
    float xn0[4], xn1[4];
    if (tid < 48) {
#pragma unroll
        for (int g = 0; g < 4; g++) {
            xn0[g] = x0[g * 192 + unit];
            xn1[g] = x1[g * 192 + unit];
        }
    }

    CLUSTER_SYNC();
    for (int t = 0; t < SS; t++) {
        float acc0 = 0.f, acc1 = 0.f;
        const float* wrow = ws + tid * 2;
#pragma unroll
        for (int p = 0; p < 24; p++) {
            float4 h2 = *(const float4*)&h01[hb + 2 * p];
            float2 wp = *(const float2*)&wrow[p * 1536];
            acc0 = fmaf(wp.x, h2.x, acc0);
            acc1 = fmaf(wp.x, h2.y, acc1);
            acc0 = fmaf(wp.y, h2.z, acc0);
            acc1 = fmaf(wp.y, h2.w, acc1);
        }
        unsigned long long pv = pk2(acc0, acc1);
        asm volatile("st.shared::cluster.b64 [%0], %1;" :: "r"(gb_remote), "l"(pv) : "memory");
        CLUSTER_SYNC();
        if (tid < 48) {
            float xc0[4], xc1[4];
#pragma unroll
            for (int g = 0; g < 4; g++) { xc0[g] = xn0[g]; xc1[g] = xn1[g]; }
            if (t + 1 < SS) {
                // issue next-step loads now: a full step of latency hiding
#pragma unroll
                for (int g = 0; g < 4; g++) {
                    xn0[g] = x0[(size_t)(t + 1) * H4 + g * 192 + unit];
                    xn1[g] = x1[(size_t)(t + 1) * H4 + g * 192 + unit];
                }
            }
            float pre0[4], pre1[4];
#pragma unroll
            for (int g = 0; g < 4; g++) {
                float2 s0 = gb[0 * 192 + g * 48 + tid];
                float2 s1 = gb[1 * 192 + g * 48 + tid];
                float2 s2 = gb[2 * 192 + g * 48 + tid];
                float2 s3 = gb[3 * 192 + g * 48 + tid];
                pre0[g] = s0.x + s1.x + s2.x + s3.x + xc0[g];
                pre1[g] = s0.y + s1.y + s2.y + s3.y + xc1[g];
            }
            float i0 = sigf(pre0[0]), f0 = sigf(pre0[1]), g0 = tanhf(pre0[2]), oo0 = sigf(pre0[3]);
            float i1 = sigf(pre1[0]), f1 = sigf(pre1[1]), g1 = tanhf(pre1[2]), oo1 = sigf(pre1[3]);
            c01.x = f0 * c01.x + i0 * g0;
            c01.y = f1 * c01.y + i1 * g1;
            float h0v = oo0 * tanhf(c01.x);
            float h1v = oo1 * tanhf(c01.y);
            unsigned long long hp = pk2(h0v, h1v);
#pragma unroll
            for (int rr = 0; rr < 4; rr++)
                asm volatile("st.shared::cluster.b64 [%0], %1;" :: "r"(hrem[rr]), "l"(hp) : "memory");
            o0[(size_t)t * OC + unit] = h0v;
            o1[(size_t)t * OC + unit] = h1v;
        }
        CLUSTER_SYNC();
    }
}

// ---------------- attention: one CTA per (b, head), 4 q-rows per warp ----------------
// K/V in smem as 16 planes of [512] float4 (plane = 4 head-dims) -> conflict-free.
#define AT_SMEM (16 * 512 * 4 * 4)
__global__ __launch_bounds__(256, 1) void attn_kernel(
    const float* __restrict__ qkv, float* __restrict__ outp) {
    extern __shared__ float sm[];
    int bh = blockIdx.x;
    int b = bh / 6, h = bh % 6;
    int tid = threadIdx.x;
    const float* base = qkv + (size_t)b * SS * QC + h * 32;
    // load K planes (0-7) and V planes (8-15); consecutive threads -> consecutive rows
    for (int i = tid; i < SS * 8; i += 256) {
        int c = i >> 9, r = i & 511;
        float4 kv = *(const float4*)(base + (size_t)r * QC + 192 + c * 4);
        float4 vv = *(const float4*)(base + (size_t)r * QC + 384 + c * 4);
        *(float4*)(sm + ((c * 512 + r) << 2)) = kv;
        *(float4*)(sm + (((8 + c) * 512 + r) << 2)) = vv;
    }
    __syncthreads();
    int wid = tid >> 5, lane = tid & 31;
    const float scale = 0.17677669529663689f;  // 1/sqrt(32)
    for (int g = 0; g < 16; g++) {
        int q0 = (g * 8 + wid) * 4;
        float s[4][16];
#pragma unroll
        for (int r = 0; r < 4; r++)
#pragma unroll
            for (int jj = 0; jj < 16; jj++) s[r][jj] = 0.f;
        // ---- scores, head-dim in 2 halves ----
#pragma unroll
        for (int dh = 0; dh < 2; dh++) {
            float qv[4][16];
#pragma unroll
            for (int r = 0; r < 4; r++)
#pragma unroll
                for (int c = 0; c < 4; c++) {
                    float4 t = *(const float4*)(base + (size_t)(q0 + r) * QC + dh * 16 + c * 4);
                    qv[r][c * 4 + 0] = t.x * scale; qv[r][c * 4 + 1] = t.y * scale;
                    qv[r][c * 4 + 2] = t.z * scale; qv[r][c * 4 + 3] = t.w * scale;
                }
            for (int jj = 0; jj < 16; jj++) {
                int krow = jj * 32 + lane;
#pragma unroll
                for (int c = 0; c < 4; c++) {
                    float4 kv = *(const float4*)(sm + (((dh * 4 + c) * 512 + krow) << 2));
#pragma unroll
                    for (int r = 0; r < 4; r++) {
                        s[r][jj] = fmaf(qv[r][c * 4 + 0], kv.x, s[r][jj]);
                        s[r][jj] = fmaf(qv[r][c * 4 + 1], kv.y, s[r][jj]);
                        s[r][jj] = fmaf(qv[r][c * 4 + 2], kv.z, s[r][jj]);
                        s[r][jj] = fmaf(qv[r][c * 4 + 3], kv.w, s[r][jj]);
                    }
                }
            }
        }
        // ---- softmax ----
        float inv[4];
#pragma unroll
        for (int r = 0; r < 4; r++) {
            float mx = -1e30f;
#pragma unroll
            for (int jj = 0; jj < 16; jj++) mx = fmaxf(mx, s[r][jj]);
#pragma unroll
            for (int off = 16; off; off >>= 1) mx = fmaxf(mx, __shfl_xor_sync(0xffffffffu, mx, off));
            float sum = 0.f;
#pragma unroll
            for (int jj = 0; jj < 16; jj++) { s[r][jj] = __expf(s[r][jj] - mx); sum += s[r][jj]; }
#pragma unroll
            for (int off = 16; off; off >>= 1) sum += __shfl_xor_sync(0xffffffffu, sum, off);
            inv[r] = 1.0f / sum;
        }
        // ---- A @ V, head-dim in 2 halves ----
#pragma unroll
        for (int dh = 0; dh < 2; dh++) {
            float o[4][16];
#pragma unroll
            for (int r = 0; r < 4; r++)
#pragma unroll
                for (int d = 0; d < 16; d++) o[r][d] = 0.f;
            for (int jj = 0; jj < 16; jj++) {
                int vrow = jj * 32 + lane;
#pragma unroll
                for (int c = 0; c < 4; c++) {
                    float4 vv = *(const float4*)(sm + (((8 + dh * 4 + c) * 512 + vrow) << 2));
#pragma unroll
                    for (int r = 0; r < 4; r++) {
                        float p = s[r][jj];
                        o[r][c * 4 + 0] = fmaf(p, vv.x, o[r][c * 4 + 0]);
                        o[r][c * 4 + 1] = fmaf(p, vv.y, o[r][c * 4 + 1]);
                        o[r][c * 4 + 2] = fmaf(p, vv.z, o[r][c * 4 + 2]);
                        o[r][c * 4 + 3] = fmaf(p, vv.w, o[r][c * 4 + 3]);
                    }
                }
            }
#pragma unroll
            for (int r = 0; r < 4; r++) {
#pragma unroll
                for (int d = 0; d < 16; d++) {
                    float v = o[r][d];
                    v += __shfl_down_sync(0xffffffffu, v, 16);
                    v += __shfl_down_sync(0xffffffffu, v, 8);
                    v += __shfl_down_sync(0xffffffffu, v, 4);
                    v += __shfl_down_sync(0xffffffffu, v, 2);
                    v += __shfl_down_sync(0xffffffffu, v, 1);
                    o[r][d] = v;
                }
                if (lane == 0) {
                    float* orow = outp + (size_t)(b * SS + q0 + r) * OC + h * 32 + dh * 16;
                    float iv = inv[r];
#pragma unroll
                    for (int c = 0; c < 4; c++)
                        *(float4*)(orow + c * 4) = make_float4(
                            o[r][c * 4 + 0] * iv, o[r][c * 4 + 1] * iv,
                            o[r][c * 4 + 2] * iv, o[r][c * 4 + 3] * iv);
                }
            }
        }
    }
}

// ---------------- fused mean over time + final projection ----------------
__global__ void mean_proj_k(const float* __restrict__ attn, const float* __restrict__ W,
                            const float* __restrict__ bias, float* __restrict__ out) {
    __shared__ float sx[OC];
    int b = blockIdx.x, c = threadIdx.x;  // 192 threads
    float s = 0.f;
    for (int t = 0; t < SS; t++) s += attn[(size_t)(b * SS + t) * OC + c];
    sx[c] = s * (1.0f / SS);
    __syncthreads();
    float acc = 0.f;
    const float* wr = W + c * OC;
    for (int k = 0; k < OC; k++) acc += sx[k] * wr[k];
    out[b * OC + c] = acc + bias[c];
}

// ---------------- launch ----------------
extern "C" void kernel_launch(void* const* d_in, const int* in_sizes, int n_in,
                              void* d_out, int out_size) {
    const float* x    = (const float*)d_in[0];
    const int*   ei   = (const int*)d_in[1];
    const float* W0   = (const float*)d_in[3];
    const float* b0   = (const float*)d_in[4];
    const float* W1   = (const float*)d_in[5];
    const float* b1   = (const float*)d_in[6];
    const float* W2   = (const float*)d_in[7];
    const float* b2   = (const float*)d_in[8];
    const float* wih  = (const float*)d_in[9];
    const float* whh  = (const float*)d_in[10];
    const float* bih  = (const float*)d_in[11];
    const float* bhh  = (const float*)d_in[12];
    const float* inW  = (const float*)d_in[13];
    const float* inB  = (const float*)d_in[14];
    const float* outW = (const float*)d_in[15];
    const float* outB = (const float*)d_in[16];
    float* out = (float*)d_out;

    float *xw, *hb, *xih, *lstm, *qkv, *attn, *dinv, *nrm, *wihT, *whhT, *inT, *gbias;
    int* deg;
    cudaGetSymbolAddress((void**)&xw, g_xw);
    cudaGetSymbolAddress((void**)&hb, g_h);
    cudaGetSymbolAddress((void**)&xih, g_xih);
    cudaGetSymbolAddress((void**)&lstm, g_lstm);
    cudaGetSymbolAddress((void**)&qkv, g_qkv);
    cudaGetSymbolAddress((void**)&attn, g_attn);
    cudaGetSymbolAddress((void**)&dinv, g_dinv);
    cudaGetSymbolAddress((void**)&deg, g_deg);
    cudaGetSymbolAddress((void**)&nrm, g_norm);
    cudaGetSymbolAddress((void**)&wihT, g_wihT);
    cudaGetSymbolAddress((void**)&whhT, g_whhT);
    cudaGetSymbolAddress((void**)&inT, g_inT);
    cudaGetSymbolAddress((void**)&gbias, g_gbias);

    cudaFuncSetAttribute(lstm_cluster_kernel, cudaFuncAttributeMaxDynamicSharedMemorySize, LSTM_SMEM);
    cudaFuncSetAttribute(attn_kernel, cudaFuncAttributeMaxDynamicSharedMemorySize, AT_SMEM);

    // prep
    const int PREP_N = 2 * H4 * 192 + QC * 192 + H4;
    prep_k<<<(PREP_N + 255) / 256, 256>>>(wih, whh, inW, bih, bhh, wihT, whhT, inT, gbias);
    zero_i32_k<<<(NN + 255) / 256, 256>>>(deg, NN);
    count_deg_k<<<(NE + 255) / 256, 256>>>(ei, deg);
    calc_dinv_k<<<(NN + 255) / 256, 256>>>(deg, dinv);
    calc_norm_k<<<(NE + 255) / 256, 256>>>(ei, dinv, nrm);

    // GCN layer 1
    sgemm2<false, false><<<dim3(128 / TN, NN / TM), 256>>>(x, W0, nullptr, xw, NN, 128, 128);
    gcn_init_k<<<(NN * 128 + 255) / 256, 256>>>(xw, b0, dinv, hb, 128);
    gcn_scatter_k<32><<<(NE * 32 + 255) / 256, 256>>>(xw, ei, nrm, hb);
    // GCN layer 2
    sgemm2<true, false><<<dim3(128 / TN, NN / TM), 256>>>(hb, W1, nullptr, xw, NN, 128, 128);
    gcn_init_k<<<(NN * 128 + 255) / 256, 256>>>(xw, b1, dinv, hb, 128);
    gcn_scatter_k<32><<<(NE * 32 + 255) / 256, 256>>>(xw, ei, nrm, hb);
    // GCN layer 3
    sgemm2<true, false><<<dim3(192 / TN, NN / TM), 256>>>(hb, W2, nullptr, xw, NN, 192, 128);
    gcn_init_k<<<(NN * 192 + 255) / 256, 256>>>(xw, b2, dinv, hb, 192);
    gcn_scatter_k<48><<<(NE * 48 + 255) / 256, 256>>>(xw, ei, nrm, hb);

    // LSTM input precompute + recurrence
    sgemm2<true, true><<<dim3(H4 / TN, NN / TM), 256>>>(hb, wihT, gbias, xih, NN, H4, 192);
    lstm_cluster_kernel<<<128, 768, LSTM_SMEM>>>(xih, whhT, lstm);
    // QKV projection
    sgemm2<false, true><<<dim3(QC / TN, NN / TM), 256>>>(lstm, inT, inB, qkv, NN, QC, 192);
    // attention
    attn_kernel<<<BB * 6, 256, AT_SMEM>>>(qkv, attn);
    // fused mean + output projection
    mean_proj_k<<<BB, OC>>>(attn, outW, outB, out);
}

// round 5
// speedup vs baseline: 2.7543x; 1.1227x over previous
#include <cuda_runtime.h>
#include <cstdint>
#include <cstddef>

#define NN 32768
#define NE 327680
#define BB 64
#define SS 512
#define OC 192
#define H4 768
#define QC 576

// ---------------- scratch (static device globals; no allocations) ----------------
__device__ float g_xw  [NN * 192];
__device__ float g_hA  [NN * 192];
__device__ float g_hB  [NN * 192];
__device__ float g_xih [(size_t)NN * H4];
__device__ float g_lstm[NN * OC];
__device__ float g_qkv [NN * QC];
__device__ float g_attn[NN * OC];
__device__ float g_dinv[NN];
__device__ int   g_deg [NN];
__device__ int   g_off [NN + 1];
__device__ int   g_cur [NN];
__device__ int2  g_elist[NE];
__device__ float g_wihT[192 * H4];
__device__ float g_whhT[192 * H4];
__device__ float g_inT [192 * QC];
__device__ float g_gbias[H4];

// ---------------- small helpers ----------------
__device__ __forceinline__ unsigned long long pk2(float a, float b) {
    unsigned long long r;
    asm("mov.b64 %0, {%1,%2};" : "=l"(r) : "f"(a), "f"(b));
    return r;
}
__device__ __forceinline__ float sigf(float x) { return 1.0f / (1.0f + __expf(-x)); }
__device__ __forceinline__ uint32_t smem_u32(const void* p) {
    uint32_t a;
    asm("{ .reg .u64 t; cvta.to.shared.u64 t, %1; cvt.u32.u64 %0, t; }" : "=r"(a) : "l"(p));
    return a;
}
#define CLUSTER_SYNC() do { \
    asm volatile("barrier.cluster.arrive.aligned;" ::: "memory"); \
    asm volatile("barrier.cluster.wait.aligned;" ::: "memory"); \
} while (0)

// ---------------- fused prep: 3 transposes + lstm bias ----------------
__global__ void prep_k(const float* __restrict__ wih, const float* __restrict__ whh,
                       const float* __restrict__ inW, const float* __restrict__ bih,
                       const float* __restrict__ bhh,
                       float* __restrict__ wihT, float* __restrict__ whhT,
                       float* __restrict__ inT, float* __restrict__ gbias) {
    int idx = blockIdx.x * blockDim.x + threadIdx.x;
    const int T1 = H4 * 192;
    const int T2 = 2 * T1;
    const int T3 = T2 + QC * 192;
    const int T4 = T3 + H4;
    if (idx < T1) {
        int r = idx / 192, c = idx % 192;
        wihT[c * H4 + r] = wih[idx];
    } else if (idx < T2) {
        int j = idx - T1;
        int r = j / 192, c = j % 192;
        whhT[c * H4 + r] = whh[j];
    } else if (idx < T3) {
        int j = idx - T2;
        int r = j / 192, c = j % 192;
        inT[c * QC + r] = inW[j];
    } else if (idx < T4) {
        int j = idx - T3;
        gbias[j] = bih[j] + bhh[j];
    }
}
__global__ void zero_i32_k(int* p, int n) {
    int i = blockIdx.x * blockDim.x + threadIdx.x;
    if (i < n) p[i] = 0;
}
__global__ void count_deg_k(const int* __restrict__ ei, int* __restrict__ deg) {
    int e = blockIdx.x * blockDim.x + threadIdx.x;
    if (e < NE) atomicAdd(&deg[ei[NE + e]], 1);
}
__global__ void calc_dinv_k(const int* __restrict__ deg, float* __restrict__ dinv) {
    int n = blockIdx.x * blockDim.x + threadIdx.x;
    if (n < NN) dinv[n] = rsqrtf((float)(deg[n] + 1));  // +1 self loop
}
// exclusive prefix over 32768 degrees; one block of 1024 threads, 32 elems each
__global__ __launch_bounds__(1024) void prefix_k(const int* __restrict__ deg,
                                                 int* __restrict__ off, int* __restrict__ cur) {
    __shared__ int part[1024];
    int tid = threadIdx.x;
    int base = tid * 32;
    int s = 0;
#pragma unroll
    for (int i = 0; i < 32; i++) s += deg[base + i];
    part[tid] = s;
    __syncthreads();
    for (int d = 1; d < 1024; d <<= 1) {
        int v = (tid >= d) ? part[tid - d] : 0;
        __syncthreads();
        part[tid] += v;
        __syncthreads();
    }
    int pre = (tid > 0) ? part[tid - 1] : 0;
#pragma unroll
    for (int i = 0; i < 32; i++) {
        off[base + i] = pre;
        cur[base + i] = pre;
        pre += deg[base + i];
    }
    if (tid == 1023) off[NN] = pre;
}
// bucket edges by destination; store (src, norm) packed
__global__ void fill_k(const int* __restrict__ ei, const float* __restrict__ dinv,
                       int* __restrict__ cur, int2* __restrict__ elist) {
    int e = blockIdx.x * blockDim.x + threadIdx.x;
    if (e >= NE) return;
    int s = ei[e], d = ei[NE + e];
    float w = dinv[s] * dinv[d];
    int pos = atomicAdd(&cur[d], 1);
    elist[pos] = make_int2(s, __float_as_int(w));
}

// ---------------- SGEMM 128x64x16 double-buffered fp32: C = op(A) @ B (+bias) ----------------
#define TM 128
#define TN 64
#define TK 16
template <bool RELU_A, bool BIAS>
__global__ __launch_bounds__(256) void sgemm2(
    const float* __restrict__ A, const float* __restrict__ Bm,
    const float* __restrict__ bias, float* __restrict__ C,
    int M, int N, int K) {
    __shared__ float As[2][TK][TM + 4];
    __shared__ float Bs[2][TK][TN];
    int tid = threadIdx.x;
    int row0 = blockIdx.y * TM, col0 = blockIdx.x * TN;
    int arow = tid >> 2, acol = (tid & 3) * 4;
    int brow = tid >> 4, bcol = (tid & 15) * 4;
    int tx = tid & 15, ty = tid >> 4;
    const float* Abase = A + (size_t)row0 * K;
    const float* Bbase = Bm + col0;

    {
        float4 a0 = *(const float4*)(Abase + (size_t)arow * K + acol);
        float4 a1 = *(const float4*)(Abase + (size_t)(arow + 64) * K + acol);
        if (RELU_A) {
            a0.x = fmaxf(a0.x, 0.f); a0.y = fmaxf(a0.y, 0.f); a0.z = fmaxf(a0.z, 0.f); a0.w = fmaxf(a0.w, 0.f);
            a1.x = fmaxf(a1.x, 0.f); a1.y = fmaxf(a1.y, 0.f); a1.z = fmaxf(a1.z, 0.f); a1.w = fmaxf(a1.w, 0.f);
        }
        As[0][acol + 0][arow] = a0.x; As[0][acol + 1][arow] = a0.y;
        As[0][acol + 2][arow] = a0.z; As[0][acol + 3][arow] = a0.w;
        As[0][acol + 0][arow + 64] = a1.x; As[0][acol + 1][arow + 64] = a1.y;
        As[0][acol + 2][arow + 64] = a1.z; As[0][acol + 3][arow + 64] = a1.w;
        *(float4*)&Bs[0][brow][bcol] = *(const float4*)(Bbase + (size_t)brow * N + bcol);
    }
    __syncthreads();

    float acc[8][4] = {};
    int nc = K / TK;
    float4 pa0, pa1, pb;
    for (int c = 0; c < nc; c++) {
        int s = c & 1;
        if (c + 1 < nc) {
            int k0 = (c + 1) * TK;
            pa0 = *(const float4*)(Abase + (size_t)arow * K + k0 + acol);
            pa1 = *(const float4*)(Abase + (size_t)(arow + 64) * K + k0 + acol);
            pb  = *(const float4*)(Bbase + (size_t)(k0 + brow) * N + bcol);
            if (RELU_A) {
                pa0.x = fmaxf(pa0.x, 0.f); pa0.y = fmaxf(pa0.y, 0.f); pa0.z = fmaxf(pa0.z, 0.f); pa0.w = fmaxf(pa0.w, 0.f);
                pa1.x = fmaxf(pa1.x, 0.f); pa1.y = fmaxf(pa1.y, 0.f); pa1.z = fmaxf(pa1.z, 0.f); pa1.w = fmaxf(pa1.w, 0.f);
            }
        }
#pragma unroll
        for (int k = 0; k < TK; k++) {
            float4 a0v = *(const float4*)&As[s][k][ty * 8];
            float4 a1v = *(const float4*)&As[s][k][ty * 8 + 4];
            float4 bv  = *(const float4*)&Bs[s][k][tx * 4];
            float am[8] = {a0v.x, a0v.y, a0v.z, a0v.w, a1v.x, a1v.y, a1v.z, a1v.w};
#pragma unroll
            for (int i = 0; i < 8; i++) {
                acc[i][0] = fmaf(am[i], bv.x, acc[i][0]);
                acc[i][1] = fmaf(am[i], bv.y, acc[i][1]);
                acc[i][2] = fmaf(am[i], bv.z, acc[i][2]);
                acc[i][3] = fmaf(am[i], bv.w, acc[i][3]);
            }
        }
        if (c + 1 < nc) {
            int d = s ^ 1;
            As[d][acol + 0][arow] = pa0.x; As[d][acol + 1][arow] = pa0.y;
            As[d][acol + 2][arow] = pa0.z; As[d][acol + 3][arow] = pa0.w;
            As[d][acol + 0][arow + 64] = pa1.x; As[d][acol + 1][arow + 64] = pa1.y;
            As[d][acol + 2][arow + 64] = pa1.z; As[d][acol + 3][arow + 64] = pa1.w;
            *(float4*)&Bs[d][brow][bcol] = pb;
        }
        __syncthreads();
    }

    float4 bv = make_float4(0.f, 0.f, 0.f, 0.f);
    if (BIAS) bv = *(const float4*)(bias + col0 + tx * 4);
#pragma unroll
    for (int i = 0; i < 8; i++) {
        float4 r = make_float4(acc[i][0] + bv.x, acc[i][1] + bv.y, acc[i][2] + bv.z, acc[i][3] + bv.w);
        *(float4*)(C + (size_t)(row0 + ty * 8 + i) * N + col0 + tx * 4) = r;
    }
}

// ---------------- GCN gather (no atomics): out[n] = bias + dinv[n]^2*xw[n] + sum_e w*xw[src] ----------------
template <int C4>
__global__ void gather_k(const float* __restrict__ xw, const int2* __restrict__ elist,
                         const int* __restrict__ off, const float* __restrict__ bias,
                         const float* __restrict__ dinv, float* __restrict__ out) {
    int idx = blockIdx.x * blockDim.x + threadIdx.x;
    if (idx >= NN * C4) return;
    int n = idx / C4, cc = idx % C4;
    const int C = C4 * 4;
    float di = dinv[n];
    float d2 = di * di;
    float4 bv = *(const float4*)(bias + cc * 4);
    float4 sv = *(const float4*)(xw + (size_t)n * C + cc * 4);
    float4 acc = make_float4(bv.x + d2 * sv.x, bv.y + d2 * sv.y,
                             bv.z + d2 * sv.z, bv.w + d2 * sv.w);
    int e0 = off[n], e1 = off[n + 1];
    for (int i = e0; i < e1; i++) {
        int2 e = __ldg(&elist[i]);
        float w = __int_as_float(e.y);
        float4 v = *(const float4*)(xw + (size_t)e.x * C + cc * 4);
        acc.x = fmaf(w, v.x, acc.x);
        acc.y = fmaf(w, v.y, acc.y);
        acc.z = fmaf(w, v.z, acc.z);
        acc.w = fmaf(w, v.w, acc.w);
    }
    *(float4*)(out + (size_t)n * C + cc * 4) = acc;
}

// ---------------- LSTM: cluster-of-4 K-split, weights in registers, x via smem prefetch ----------------
__global__ __launch_bounds__(768, 1) __cluster_dims__(4, 1, 1)
void lstm_cluster_kernel(const float* __restrict__ xih, const float* __restrict__ whhT,
                         float* __restrict__ out) {
    __shared__ __align__(16) float2 h01[192];       // h for (b0,b1)
    __shared__ __align__(16) float2 gb[4 * 192];    // partial gates [4 src][192 slots]
    __shared__ float2 xs[2][768];                   // x gate inputs ping-pong
    float wreg[48];
    int tid = threadIdx.x;
    uint32_t rank;
    asm("mov.u32 %0, %%cluster_ctarank;" : "=r"(rank));
    int b0 = (blockIdx.x >> 2) * 2;

    // this thread's gate-row slice of whh: w[j=tid][k] for k in [48*rank, 48*rank+48)
#pragma unroll
    for (int k = 0; k < 48; k++)
        wreg[k] = whhT[(size_t)(rank * 48 + k) * 768 + tid];
    if (tid < 192) h01[tid] = make_float2(0.f, 0.f);

    int gidx = tid / 192, u192 = tid % 192;
    uint32_t ro = (uint32_t)(u192 / 48);
    int slot = gidx * 48 + (u192 % 48);
    uint32_t gb_local = smem_u32(&gb[rank * 192 + slot]);
    uint32_t gb_remote;
    asm("mapa.shared::cluster.u32 %0, %1, %2;" : "=r"(gb_remote) : "r"(gb_local), "r"(ro));

    float2 c01 = make_float2(0.f, 0.f);
    int unit = rank * 48 + tid;
    uint32_t hrem[4];
    if (tid < 48) {
        uint32_t hl = smem_u32(&h01[unit]);
#pragma unroll
        for (uint32_t rr = 0; rr < 4; rr++)
            asm("mapa.shared::cluster.u32 %0, %1, %2;" : "=r"(hrem[rr]) : "r"(hl), "r"(rr));
    }
    const float* x0 = xih + (size_t)b0 * SS * H4;
    const float* x1 = x0 + (size_t)SS * H4;
    float* o0 = out + (size_t)b0 * SS * OC;
    float* o1 = o0 + (size_t)SS * OC;
    const int hb = (int)rank * 48;

    // prefill x for t=0
    xs[0][tid] = make_float2(x0[tid], x1[tid]);

    CLUSTER_SYNC();
    for (int t = 0; t < SS; t++) {
        float acc0 = 0.f, acc1 = 0.f;
#pragma unroll
        for (int p = 0; p < 24; p++) {
            float4 h2 = *(const float4*)&h01[hb + 2 * p];
            acc0 = fmaf(wreg[2 * p], h2.x, acc0);
            acc1 = fmaf(wreg[2 * p], h2.y, acc1);
            acc0 = fmaf(wreg[2 * p + 1], h2.z, acc0);
            acc1 = fmaf(wreg[2 * p + 1], h2.w, acc1);
        }
        unsigned long long pv = pk2(acc0, acc1);
        asm volatile("st.shared::cluster.b64 [%0], %1;" :: "r"(gb_remote), "l"(pv) : "memory");
        // issue next-step x loads: latency hides under the cluster barrier
        float nx0 = 0.f, nx1 = 0.f;
        bool pf = (t + 1 < SS);
        if (pf) {
            nx0 = x0[(size_t)(t + 1) * H4 + tid];
            nx1 = x1[(size_t)(t + 1) * H4 + tid];
        }
        CLUSTER_SYNC();
        if (pf) xs[(t + 1) & 1][tid] = make_float2(nx0, nx1);
        if (tid < 48) {
            const float2* xrow = xs[t & 1];
            float pre0[4], pre1[4];
#pragma unroll
            for (int g = 0; g < 4; g++) {
                float2 s0 = gb[0 * 192 + g * 48 + tid];
                float2 s1 = gb[1 * 192 + g * 48 + tid];
                float2 s2 = gb[2 * 192 + g * 48 + tid];
                float2 s3 = gb[3 * 192 + g * 48 + tid];
                float2 xg = xrow[g * 192 + unit];
                pre0[g] = s0.x + s1.x + s2.x + s3.x + xg.x;
                pre1[g] = s0.y + s1.y + s2.y + s3.y + xg.y;
            }
            float i0 = sigf(pre0[0]), f0 = sigf(pre0[1]), g0 = tanhf(pre0[2]), oo0 = sigf(pre0[3]);
            float i1 = sigf(pre1[0]), f1 = sigf(pre1[1]), g1 = tanhf(pre1[2]), oo1 = sigf(pre1[3]);
            c01.x = f0 * c01.x + i0 * g0;
            c01.y = f1 * c01.y + i1 * g1;
            float h0v = oo0 * tanhf(c01.x);
            float h1v = oo1 * tanhf(c01.y);
            unsigned long long hp = pk2(h0v, h1v);
#pragma unroll
            for (int rr = 0; rr < 4; rr++)
                asm volatile("st.shared::cluster.b64 [%0], %1;" :: "r"(hrem[rr]), "l"(hp) : "memory");
            o0[(size_t)t * OC + unit] = h0v;
            o1[(size_t)t * OC + unit] = h1v;
        }
        CLUSTER_SYNC();
    }
}

// ---------------- attention: one CTA per (b, head), 4 q-rows per warp ----------------
#define AT_SMEM (16 * 512 * 4 * 4)
__global__ __launch_bounds__(256, 1) void attn_kernel(
    const float* __restrict__ qkv, float* __restrict__ outp) {
    extern __shared__ float sm[];
    int bh = blockIdx.x;
    int b = bh / 6, h = bh % 6;
    int tid = threadIdx.x;
    const float* base = qkv + (size_t)b * SS * QC + h * 32;
    for (int i = tid; i < SS * 8; i += 256) {
        int c = i >> 9, r = i & 511;
        float4 kv = *(const float4*)(base + (size_t)r * QC + 192 + c * 4);
        float4 vv = *(const float4*)(base + (size_t)r * QC + 384 + c * 4);
        *(float4*)(sm + ((c * 512 + r) << 2)) = kv;
        *(float4*)(sm + (((8 + c) * 512 + r) << 2)) = vv;
    }
    __syncthreads();
    int wid = tid >> 5, lane = tid & 31;
    const float scale = 0.17677669529663689f;  // 1/sqrt(32)
    for (int g = 0; g < 16; g++) {
        int q0 = (g * 8 + wid) * 4;
        float s[4][16];
#pragma unroll
        for (int r = 0; r < 4; r++)
#pragma unroll
            for (int jj = 0; jj < 16; jj++) s[r][jj] = 0.f;
#pragma unroll
        for (int dh = 0; dh < 2; dh++) {
            float qv[4][16];
#pragma unroll
            for (int r = 0; r < 4; r++)
#pragma unroll
                for (int c = 0; c < 4; c++) {
                    float4 t = *(const float4*)(base + (size_t)(q0 + r) * QC + dh * 16 + c * 4);
                    qv[r][c * 4 + 0] = t.x * scale; qv[r][c * 4 + 1] = t.y * scale;
                    qv[r][c * 4 + 2] = t.z * scale; qv[r][c * 4 + 3] = t.w * scale;
                }
            for (int jj = 0; jj < 16; jj++) {
                int krow = jj * 32 + lane;
#pragma unroll
                for (int c = 0; c < 4; c++) {
                    float4 kv = *(const float4*)(sm + (((dh * 4 + c) * 512 + krow) << 2));
#pragma unroll
                    for (int r = 0; r < 4; r++) {
                        s[r][jj] = fmaf(qv[r][c * 4 + 0], kv.x, s[r][jj]);
                        s[r][jj] = fmaf(qv[r][c * 4 + 1], kv.y, s[r][jj]);
                        s[r][jj] = fmaf(qv[r][c * 4 + 2], kv.z, s[r][jj]);
                        s[r][jj] = fmaf(qv[r][c * 4 + 3], kv.w, s[r][jj]);
                    }
                }
            }
        }
        float inv[4];
#pragma unroll
        for (int r = 0; r < 4; r++) {
            float mx = -1e30f;
#pragma unroll
            for (int jj = 0; jj < 16; jj++) mx = fmaxf(mx, s[r][jj]);
#pragma unroll
            for (int off = 16; off; off >>= 1) mx = fmaxf(mx, __shfl_xor_sync(0xffffffffu, mx, off));
            float sum = 0.f;
#pragma unroll
            for (int jj = 0; jj < 16; jj++) { s[r][jj] = __expf(s[r][jj] - mx); sum += s[r][jj]; }
#pragma unroll
            for (int off = 16; off; off >>= 1) sum += __shfl_xor_sync(0xffffffffu, sum, off);
            inv[r] = 1.0f / sum;
        }
#pragma unroll
        for (int dh = 0; dh < 2; dh++) {
            float o[4][16];
#pragma unroll
            for (int r = 0; r < 4; r++)
#pragma unroll
                for (int d = 0; d < 16; d++) o[r][d] = 0.f;
            for (int jj = 0; jj < 16; jj++) {
                int vrow = jj * 32 + lane;
#pragma unroll
                for (int c = 0; c < 4; c++) {
                    float4 vv = *(const float4*)(sm + (((8 + dh * 4 + c) * 512 + vrow) << 2));
#pragma unroll
                    for (int r = 0; r < 4; r++) {
                        float p = s[r][jj];
                        o[r][c * 4 + 0] = fmaf(p, vv.x, o[r][c * 4 + 0]);
                        o[r][c * 4 + 1] = fmaf(p, vv.y, o[r][c * 4 + 1]);
                        o[r][c * 4 + 2] = fmaf(p, vv.z, o[r][c * 4 + 2]);
                        o[r][c * 4 + 3] = fmaf(p, vv.w, o[r][c * 4 + 3]);
                    }
                }
            }
#pragma unroll
            for (int r = 0; r < 4; r++) {
#pragma unroll
                for (int d = 0; d < 16; d++) {
                    float v = o[r][d];
                    v += __shfl_down_sync(0xffffffffu, v, 16);
                    v += __shfl_down_sync(0xffffffffu, v, 8);
                    v += __shfl_down_sync(0xffffffffu, v, 4);
                    v += __shfl_down_sync(0xffffffffu, v, 2);
                    v += __shfl_down_sync(0xffffffffu, v, 1);
                    o[r][d] = v;
                }
                if (lane == 0) {
                    float* orow = outp + (size_t)(b * SS + q0 + r) * OC + h * 32 + dh * 16;
                    float iv = inv[r];
#pragma unroll
                    for (int c = 0; c < 4; c++)
                        *(float4*)(orow + c * 4) = make_float4(
                            o[r][c * 4 + 0] * iv, o[r][c * 4 + 1] * iv,
                            o[r][c * 4 + 2] * iv, o[r][c * 4 + 3] * iv);
                }
            }
        }
    }
}

// ---------------- fused mean over time + final projection ----------------
__global__ void mean_proj_k(const float* __restrict__ attn, const float* __restrict__ W,
                            const float* __restrict__ bias, float* __restrict__ out) {
    __shared__ float sx[OC];
    int b = blockIdx.x, c = threadIdx.x;  // 192 threads
    float s = 0.f;
    for (int t = 0; t < SS; t++) s += attn[(size_t)(b * SS + t) * OC + c];
    sx[c] = s * (1.0f / SS);
    __syncthreads();
    float acc = 0.f;
    const float* wr = W + c * OC;
    for (int k = 0; k < OC; k++) acc += sx[k] * wr[k];
    out[b * OC + c] = acc + bias[c];
}

// ---------------- launch ----------------
extern "C" void kernel_launch(void* const* d_in, const int* in_sizes, int n_in,
                              void* d_out, int out_size) {
    const float* x    = (const float*)d_in[0];
    const int*   ei   = (const int*)d_in[1];
    const float* W0   = (const float*)d_in[3];
    const float* b0   = (const float*)d_in[4];
    const float* W1   = (const float*)d_in[5];
    const float* b1   = (const float*)d_in[6];
    const float* W2   = (const float*)d_in[7];
    const float* b2   = (const float*)d_in[8];
    const float* wih  = (const float*)d_in[9];
    const float* whh  = (const float*)d_in[10];
    const float* bih  = (const float*)d_in[11];
    const float* bhh  = (const float*)d_in[12];
    const float* inW  = (const float*)d_in[13];
    const float* inB  = (const float*)d_in[14];
    const float* outW = (const float*)d_in[15];
    const float* outB = (const float*)d_in[16];
    float* out = (float*)d_out;

    float *xw, *hA, *hB, *xih, *lstm, *qkv, *attn, *dinv, *wihT, *whhT, *inT, *gbias;
    int *deg, *off, *cur;
    int2* elist;
    cudaGetSymbolAddress((void**)&xw, g_xw);
    cudaGetSymbolAddress((void**)&hA, g_hA);
    cudaGetSymbolAddress((void**)&hB, g_hB);
    cudaGetSymbolAddress((void**)&xih, g_xih);
    cudaGetSymbolAddress((void**)&lstm, g_lstm);
    cudaGetSymbolAddress((void**)&qkv, g_qkv);
    cudaGetSymbolAddress((void**)&attn, g_attn);
    cudaGetSymbolAddress((void**)&dinv, g_dinv);
    cudaGetSymbolAddress((void**)&deg, g_deg);
    cudaGetSymbolAddress((void**)&off, g_off);
    cudaGetSymbolAddress((void**)&cur, g_cur);
    cudaGetSymbolAddress((void**)&elist, g_elist);
    cudaGetSymbolAddress((void**)&wihT, g_wihT);
    cudaGetSymbolAddress((void**)&whhT, g_whhT);
    cudaGetSymbolAddress((void**)&inT, g_inT);
    cudaGetSymbolAddress((void**)&gbias, g_gbias);

    cudaFuncSetAttribute(attn_kernel, cudaFuncAttributeMaxDynamicSharedMemorySize, AT_SMEM);

    // prep: transposes + bias, degree count, dinv, bucket edges by dst
    const int PREP_N = 2 * H4 * 192 + QC * 192 + H4;
    prep_k<<<(PREP_N + 255) / 256, 256>>>(wih, whh, inW, bih, bhh, wihT, whhT, inT, gbias);
    zero_i32_k<<<(NN + 255) / 256, 256>>>(deg, NN);
    count_deg_k<<<(NE + 255) / 256, 256>>>(ei, deg);
    calc_dinv_k<<<(NN + 255) / 256, 256>>>(deg, dinv);
    prefix_k<<<1, 1024>>>(deg, off, cur);
    fill_k<<<(NE + 255) / 256, 256>>>(ei, dinv, cur, elist);

    // GCN layer 1
    sgemm2<false, false><<<dim3(128 / TN, NN / TM), 256>>>(x, W0, nullptr, xw, NN, 128, 128);
    gather_k<32><<<(NN * 32 + 255) / 256, 256>>>(xw, elist, off, b0, dinv, hA);
    // GCN layer 2
    sgemm2<true, false><<<dim3(128 / TN, NN / TM), 256>>>(hA, W1, nullptr, xw, NN, 128, 128);
    gather_k<32><<<(NN * 32 + 255) / 256, 256>>>(xw, elist, off, b1, dinv, hB);
    // GCN layer 3
    sgemm2<true, false><<<dim3(192 / TN, NN / TM), 256>>>(hB, W2, nullptr, xw, NN, 192, 128);
    gather_k<48><<<(NN * 48 + 255) / 256, 256>>>(xw, elist, off, b2, dinv, hA);

    // LSTM input precompute + recurrence
    sgemm2<true, true><<<dim3(H4 / TN, NN / TM), 256>>>(hA, wihT, gbias, xih, NN, H4, 192);
    lstm_cluster_kernel<<<128, 768>>>(xih, whhT, lstm);
    // QKV projection
    sgemm2<false, true><<<dim3(QC / TN, NN / TM), 256>>>(lstm, inT, inB, qkv, NN, QC, 192);
    // attention
    attn_kernel<<<BB * 6, 256, AT_SMEM>>>(qkv, attn);
    // fused mean + output projection
    mean_proj_k<<<BB, OC>>>(attn, outW, outB, out);
}